// round 1
// baseline (speedup 1.0000x reference)
#include <cuda_runtime.h>
#include <math.h>

// Problem: TtMambaSSM  (B=256, D=5120, DT_RANK=160, N=16)
// Inputs (metadata order): x, W_dt_low, W_dt, b_dt, W_B, W_C, A, D, h0  (all float32)
// Output: (1,1,256,5120) float32
//
// Pipeline:
//   zero_kernel  : clear split-K accumulator scratch
//   gemm1_kernel : TBC[b][0:160]=x@W_dt_low, [160:176]=x@W_B, [176:192]=x@W_C  (split-K + atomics)
//   bc_kernel    : BC[b] = sum_n Bp[b][n]*Cp[b][n]
//   ssm_kernel   : delta = softplus(T@W_dt + b_dt);
//                  out = x*(D + delta*BC) + sum_n exp(delta*A)*h0*Cp   (fused, h0 read once)

typedef unsigned long long ull;

#define Bsz 256
#define Dsz 5120
#define NC  192   // 160 (T) + 16 (Bp) + 16 (Cp)

__device__ float g_TBC[Bsz * NC];
__device__ float g_BC[Bsz];

// ---- packed fp32x2 FMA helpers (Blackwell FFMA2) ----
__device__ __forceinline__ ull pack2(float lo, float hi) {
    ull r; asm("mov.b64 %0, {%1, %2};" : "=l"(r) : "f"(lo), "f"(hi)); return r;
}
__device__ __forceinline__ void ffma2(ull& d, ull a, ull b) {
    asm("fma.rn.f32x2 %0, %1, %2, %0;" : "+l"(d) : "l"(a), "l"(b));
}
__device__ __forceinline__ float2 unpack2(ull v) {
    float2 f; asm("mov.b64 {%0, %1}, %2;" : "=f"(f.x), "=f"(f.y) : "l"(v)); return f;
}

__global__ void zero_kernel() {
    int i = blockIdx.x * 256 + threadIdx.x;
    if (i < Bsz * NC) g_TBC[i] = 0.0f;
}

// ---------------- GEMM1: 256 x 192 x 5120, split-K ----------------
// grid = (12, 40): 4 m-tiles(64) x 3 n-tiles(64), K split into 40 chunks of 128
__global__ void __launch_bounds__(256) gemm1_kernel(
    const float* __restrict__ x, const float* __restrict__ Wlow,
    const float* __restrict__ WB, const float* __restrict__ WC)
{
    __shared__ float As[16][68];   // [k][m], padded
    __shared__ float Bs[16][64];   // [k][n]

    const int m0 = (blockIdx.x & 3) * 64;
    const int n0 = (blockIdx.x >> 2) * 64;
    const int k0 = blockIdx.y * 128;
    const int tid = threadIdx.x;
    const int ty = tid >> 4, tx = tid & 15;

    ull acc[2][4];
    const ull z0 = pack2(0.0f, 0.0f);
#pragma unroll
    for (int p = 0; p < 2; p++)
#pragma unroll
        for (int j = 0; j < 4; j++) acc[p][j] = z0;

    const int lm  = tid >> 2;          // 0..63
    const int lkq = (tid & 3) * 4;     // 0,4,8,12
    const int lkk = tid >> 4;          // 0..15
    const int lj4 = (tid & 15) * 4;    // 0..60

    for (int kb = k0; kb < k0 + 128; kb += 16) {
        float4 av = *(const float4*)(x + (m0 + lm) * Dsz + kb + lkq);
        As[lkq + 0][lm] = av.x;
        As[lkq + 1][lm] = av.y;
        As[lkq + 2][lm] = av.z;
        As[lkq + 3][lm] = av.w;
        {
            const int k = kb + lkk;
#pragma unroll
            for (int q = 0; q < 4; q++) {
                const int j = n0 + lj4 + q;
                float w;
                if (j < 160)      w = Wlow[k * 160 + j];
                else if (j < 176) w = WB[k * 16 + (j - 160)];
                else              w = WC[k * 16 + (j - 176)];
                Bs[lkk][lj4 + q] = w;
            }
        }
        __syncthreads();
#pragma unroll
        for (int kk = 0; kk < 16; kk++) {
            float4 a = *(const float4*)&As[kk][ty * 4];
            float4 b = *(const float4*)&Bs[kk][tx * 4];
            ull aP0 = pack2(a.x, a.y);
            ull aP1 = pack2(a.z, a.w);
            ull bd;
            bd = pack2(b.x, b.x); ffma2(acc[0][0], aP0, bd); ffma2(acc[1][0], aP1, bd);
            bd = pack2(b.y, b.y); ffma2(acc[0][1], aP0, bd); ffma2(acc[1][1], aP1, bd);
            bd = pack2(b.z, b.z); ffma2(acc[0][2], aP0, bd); ffma2(acc[1][2], aP1, bd);
            bd = pack2(b.w, b.w); ffma2(acc[0][3], aP0, bd); ffma2(acc[1][3], aP1, bd);
        }
        __syncthreads();
    }
#pragma unroll
    for (int p = 0; p < 2; p++)
#pragma unroll
        for (int j = 0; j < 4; j++) {
            float2 v = unpack2(acc[p][j]);
            const int row = m0 + ty * 4 + 2 * p;
            const int col = n0 + tx * 4 + j;
            atomicAdd(&g_TBC[row * NC + col], v.x);
            atomicAdd(&g_TBC[(row + 1) * NC + col], v.y);
        }
}

__global__ void bc_kernel() {
    const int b = threadIdx.x;
    float s = 0.0f;
#pragma unroll
    for (int n = 0; n < 16; n++)
        s += g_TBC[b * NC + 160 + n] * g_TBC[b * NC + 176 + n];
    g_BC[b] = s;
}

// ---------------- fused SSM kernel ----------------
// grid = (80, 8): d-tiles of 64, b-tiles of 32. 128 threads, 4x4 micro-tile.
__global__ void __launch_bounds__(128) ssm_kernel(
    const float* __restrict__ x, const float* __restrict__ Wdt,
    const float* __restrict__ bias, const float* __restrict__ Ag,
    const float* __restrict__ Dg, const float* __restrict__ h0,
    float* __restrict__ out)
{
    __shared__ float Ts[32][36];     // [k][b], padded
    __shared__ float Ws[32][64];     // [k][d]
    __shared__ float A_s[64][17];    // [d][n], padded (avoid 16-way conflicts)
    __shared__ float Cp_s[32][16];   // [b][n]
    __shared__ float bias_s[64];
    __shared__ float D_s[64];
    __shared__ float BC_s[32];

    const int d0 = blockIdx.x * 64;
    const int b0 = blockIdx.y * 32;
    const int tid = threadIdx.x;
    const int ty = tid >> 4, tx = tid & 15;   // ty 0..7, tx 0..15

    // phase-0: small per-tile operand loads
    {
        // A tile: 64 x 16, 8 scalars per thread (coalesced reads)
        const int f0 = tid * 8;
#pragma unroll
        for (int s = 0; s < 8; s++) {
            const int f = f0 + s;
            A_s[f >> 4][f & 15] = Ag[(d0 << 4) + f];
        }
    }
    {
        const int r = tid >> 2;          // 0..31
        const int q = (tid & 3) * 4;
        *(float4*)&Cp_s[r][q] = *(const float4*)(g_TBC + (b0 + r) * NC + 176 + q);
    }
    if (tid < 64) {
        bias_s[tid] = bias[d0 + tid];
        D_s[tid]    = Dg[d0 + tid];
    }
    if (tid < 32) BC_s[tid] = g_BC[b0 + tid];

    // ---- GEMM2: delta_lin[b][d] = T[b][:] . W_dt[:][d], K = 160 ----
    ull acc[2][4];
    const ull z0 = pack2(0.0f, 0.0f);
#pragma unroll
    for (int p = 0; p < 2; p++)
#pragma unroll
        for (int j = 0; j < 4; j++) acc[p][j] = z0;

    const int lbb = tid >> 2;           // 0..31
    const int kqa = (tid & 3) * 4;      // 0,4,8,12
    const int lkk = tid >> 3;           // 0..15
    const int ldq = (tid & 7) * 8;      // 0..56

    for (int kb = 0; kb < 160; kb += 32) {
        float4 t0 = *(const float4*)(g_TBC + (b0 + lbb) * NC + kb + kqa);
        float4 t1 = *(const float4*)(g_TBC + (b0 + lbb) * NC + kb + kqa + 16);
        Ts[kqa + 0][lbb] = t0.x;  Ts[kqa + 1][lbb] = t0.y;
        Ts[kqa + 2][lbb] = t0.z;  Ts[kqa + 3][lbb] = t0.w;
        Ts[kqa + 16][lbb] = t1.x; Ts[kqa + 17][lbb] = t1.y;
        Ts[kqa + 18][lbb] = t1.z; Ts[kqa + 19][lbb] = t1.w;
#pragma unroll
        for (int rr = 0; rr < 2; rr++) {
            const int kk = lkk + rr * 16;
            *(float4*)&Ws[kk][ldq]     = *(const float4*)(Wdt + (kb + kk) * Dsz + d0 + ldq);
            *(float4*)&Ws[kk][ldq + 4] = *(const float4*)(Wdt + (kb + kk) * Dsz + d0 + ldq + 4);
        }
        __syncthreads();
#pragma unroll
        for (int kk = 0; kk < 32; kk++) {
            float4 a = *(const float4*)&Ts[kk][ty * 4];
            float4 b = *(const float4*)&Ws[kk][tx * 4];
            ull aP0 = pack2(a.x, a.y);
            ull aP1 = pack2(a.z, a.w);
            ull bd;
            bd = pack2(b.x, b.x); ffma2(acc[0][0], aP0, bd); ffma2(acc[1][0], aP1, bd);
            bd = pack2(b.y, b.y); ffma2(acc[0][1], aP0, bd); ffma2(acc[1][1], aP1, bd);
            bd = pack2(b.z, b.z); ffma2(acc[0][2], aP0, bd); ffma2(acc[1][2], aP1, bd);
            bd = pack2(b.w, b.w); ffma2(acc[0][3], aP0, bd); ffma2(acc[1][3], aP1, bd);
        }
        __syncthreads();
    }

    // ---- softplus (threshold 20, matches reference) ----
    float dl[4][4];
#pragma unroll
    for (int p = 0; p < 2; p++)
#pragma unroll
        for (int j = 0; j < 4; j++) {
            float2 v = unpack2(acc[p][j]);
            dl[2 * p][j]     = v.x;
            dl[2 * p + 1][j] = v.y;
        }
#pragma unroll
    for (int r = 0; r < 4; r++)
#pragma unroll
        for (int j = 0; j < 4; j++) {
            float t = dl[r][j] + bias_s[tx * 4 + j];
            dl[r][j] = (t > 20.0f) ? t : log1pf(expf(t));
        }

    // ---- state update + C reduction + skip, h0 streamed once ----
#pragma unroll
    for (int r = 0; r < 4; r++) {
        const int bl = ty * 4 + r;       // 0..31
        const int b  = b0 + bl;
        float4 xv = *(const float4*)(x + (size_t)b * Dsz + d0 + tx * 4);
        float xa[4] = {xv.x, xv.y, xv.z, xv.w};
        float o[4];
#pragma unroll
        for (int j = 0; j < 4; j++) {
            const int dloc = tx * 4 + j;
            const float delta = dl[r][j];
            const float4* hp = (const float4*)(h0 + ((size_t)b * Dsz + (d0 + dloc)) * 16);
            float y0 = 0.0f, y1 = 0.0f, y2 = 0.0f, y3 = 0.0f;
#pragma unroll
            for (int nq = 0; nq < 4; nq++) {
                float4 h = hp[nq];
                const float* Ar = &A_s[dloc][nq * 4];
                const float* Cr = &Cp_s[bl][nq * 4];
                y0 += __expf(delta * Ar[0]) * (h.x * Cr[0]);
                y1 += __expf(delta * Ar[1]) * (h.y * Cr[1]);
                y2 += __expf(delta * Ar[2]) * (h.z * Cr[2]);
                y3 += __expf(delta * Ar[3]) * (h.w * Cr[3]);
            }
            o[j] = xa[j] * (D_s[dloc] + delta * BC_s[bl]) + (y0 + y1) + (y2 + y3);
        }
        *(float4*)(out + (size_t)b * Dsz + d0 + tx * 4) = make_float4(o[0], o[1], o[2], o[3]);
    }
}

extern "C" void kernel_launch(void* const* d_in, const int* in_sizes, int n_in,
                              void* d_out, int out_size) {
    const float* x    = (const float*)d_in[0];
    const float* Wlow = (const float*)d_in[1];
    const float* Wdt  = (const float*)d_in[2];
    const float* bdt  = (const float*)d_in[3];
    const float* WB   = (const float*)d_in[4];
    const float* WC   = (const float*)d_in[5];
    const float* A    = (const float*)d_in[6];
    const float* D    = (const float*)d_in[7];
    const float* h0   = (const float*)d_in[8];
    float* out = (float*)d_out;

    zero_kernel<<<(Bsz * NC) / 256, 256>>>();
    gemm1_kernel<<<dim3(12, 40), 256>>>(x, Wlow, WB, WC);
    bc_kernel<<<1, 256>>>();
    ssm_kernel<<<dim3(80, 8), 128>>>(x, Wdt, bdt, A, D, h0, out);
}

// round 2
// speedup vs baseline: 1.4406x; 1.4406x over previous
#include <cuda_runtime.h>
#include <math.h>

// TtMambaSSM (B=256, D=5120, R=160, N=16)
// Pipeline:
//   prep  : Wcat = [W_dt_low | W_B | W_C] (5120 x 192), zero TBC accumulator
//   gemm1 : TBC = x @ Wcat                (256 x 192, split-K + atomics)
//   gemm2 : delta = softplus(T @ W_dt + b_dt)  (256 x 5120)
//   elem  : out = x*(D + delta*BC) + sum_n exp(delta*A)*h0*Cp   (h0 coalesced)

typedef unsigned long long ull;

#define Bsz 256
#define Dsz 5120
#define Rk  160
#define NC  192

__device__ float g_Wcat[Dsz * NC];
__device__ float g_TBC[Bsz * NC];
__device__ float g_delta[Bsz * Dsz];

// ---- packed fp32x2 FMA (Blackwell FFMA2 via PTX) ----
__device__ __forceinline__ ull pack2(float lo, float hi) {
    ull r; asm("mov.b64 %0, {%1, %2};" : "=l"(r) : "f"(lo), "f"(hi)); return r;
}
__device__ __forceinline__ void ffma2(ull& d, ull a, ull b) {
    asm("fma.rn.f32x2 %0, %1, %2, %0;" : "+l"(d) : "l"(a), "l"(b));
}
__device__ __forceinline__ float2 unpack2(ull v) {
    float2 f; asm("mov.b64 {%0, %1}, %2;" : "=f"(f.x), "=f"(f.y) : "l"(v)); return f;
}

// ---------------- prep: concat weights + zero accumulator ----------------
__global__ void prep_kernel(const float* __restrict__ Wlow,
                            const float* __restrict__ WB,
                            const float* __restrict__ WC)
{
    int idx = blockIdx.x * 256 + threadIdx.x;
    if (idx < Dsz * NC) {
        int k = idx / NC, j = idx - k * NC;
        float w;
        if (j < 160)      w = Wlow[k * 160 + j];
        else if (j < 176) w = WB[k * 16 + (j - 160)];
        else              w = WC[k * 16 + (j - 176)];
        g_Wcat[idx] = w;
    } else {
        int t = idx - Dsz * NC;
        if (t < Bsz * NC) g_TBC[t] = 0.0f;
    }
}

// ---------------- GEMM1: 256 x 192 x 5120, split-K=40 ----------------
// grid = (12, 40): 4 m-tiles(64) x 3 n-tiles(64), k-chunk 128
__global__ void __launch_bounds__(256) gemm1_kernel(const float* __restrict__ x)
{
    __shared__ float As[16][68];   // [k][m] padded
    __shared__ float Bs[16][64];   // [k][n]

    const int m0 = (blockIdx.x & 3) * 64;
    const int n0 = (blockIdx.x >> 2) * 64;
    const int k0 = blockIdx.y * 128;
    const int tid = threadIdx.x;
    const int ty = tid >> 4, tx = tid & 15;
    const int lm  = tid >> 2, lkq = (tid & 3) * 4;
    const int lkk = tid >> 4, lj4 = (tid & 15) * 4;

    ull acc[2][4];
    const ull z0 = pack2(0.0f, 0.0f);
#pragma unroll
    for (int p = 0; p < 2; p++)
#pragma unroll
        for (int j = 0; j < 4; j++) acc[p][j] = z0;

    // register prefetch pipeline
    float4 av = *(const float4*)(x + (m0 + lm) * Dsz + k0 + lkq);
    float4 bv = *(const float4*)(g_Wcat + (k0 + lkk) * NC + n0 + lj4);

    for (int it = 0; it < 8; it++) {
        As[lkq + 0][lm] = av.x;
        As[lkq + 1][lm] = av.y;
        As[lkq + 2][lm] = av.z;
        As[lkq + 3][lm] = av.w;
        *(float4*)&Bs[lkk][lj4] = bv;
        __syncthreads();
        if (it < 7) {
            const int kb = k0 + (it + 1) * 16;
            av = *(const float4*)(x + (m0 + lm) * Dsz + kb + lkq);
            bv = *(const float4*)(g_Wcat + (kb + lkk) * NC + n0 + lj4);
        }
#pragma unroll
        for (int kk = 0; kk < 16; kk++) {
            float4 a = *(const float4*)&As[kk][ty * 4];
            float4 b = *(const float4*)&Bs[kk][tx * 4];
            ull aP0 = pack2(a.x, a.y);
            ull aP1 = pack2(a.z, a.w);
            ull bd;
            bd = pack2(b.x, b.x); ffma2(acc[0][0], aP0, bd); ffma2(acc[1][0], aP1, bd);
            bd = pack2(b.y, b.y); ffma2(acc[0][1], aP0, bd); ffma2(acc[1][1], aP1, bd);
            bd = pack2(b.z, b.z); ffma2(acc[0][2], aP0, bd); ffma2(acc[1][2], aP1, bd);
            bd = pack2(b.w, b.w); ffma2(acc[0][3], aP0, bd); ffma2(acc[1][3], aP1, bd);
        }
        __syncthreads();
    }
#pragma unroll
    for (int p = 0; p < 2; p++)
#pragma unroll
        for (int j = 0; j < 4; j++) {
            float2 v = unpack2(acc[p][j]);
            const int row = m0 + ty * 4 + 2 * p;
            const int col = n0 + tx * 4 + j;
            atomicAdd(&g_TBC[row * NC + col], v.x);
            atomicAdd(&g_TBC[(row + 1) * NC + col], v.y);
        }
}

// ---------------- GEMM2: delta = softplus(T @ W_dt + b), 256 x 5120 x 160 ----------------
// grid = (80, 4): n-tiles(64) x m-tiles(64), full K in-block
__global__ void __launch_bounds__(256) gemm2_kernel(const float* __restrict__ Wdt,
                                                    const float* __restrict__ bias)
{
    __shared__ float As[16][68];
    __shared__ float Bs[16][64];
    __shared__ float bias_s[64];

    const int n0 = blockIdx.x * 64;
    const int m0 = blockIdx.y * 64;
    const int tid = threadIdx.x;
    const int ty = tid >> 4, tx = tid & 15;
    const int lm  = tid >> 2, lkq = (tid & 3) * 4;
    const int lkk = tid >> 4, lj4 = (tid & 15) * 4;

    if (tid < 64) bias_s[tid] = bias[n0 + tid];

    ull acc[2][4];
    const ull z0 = pack2(0.0f, 0.0f);
#pragma unroll
    for (int p = 0; p < 2; p++)
#pragma unroll
        for (int j = 0; j < 4; j++) acc[p][j] = z0;

    float4 av = *(const float4*)(g_TBC + (m0 + lm) * NC + lkq);
    float4 bv = *(const float4*)(Wdt + lkk * Dsz + n0 + lj4);

    for (int it = 0; it < 10; it++) {
        As[lkq + 0][lm] = av.x;
        As[lkq + 1][lm] = av.y;
        As[lkq + 2][lm] = av.z;
        As[lkq + 3][lm] = av.w;
        *(float4*)&Bs[lkk][lj4] = bv;
        __syncthreads();
        if (it < 9) {
            const int kb = (it + 1) * 16;
            av = *(const float4*)(g_TBC + (m0 + lm) * NC + kb + lkq);
            bv = *(const float4*)(Wdt + (kb + lkk) * Dsz + n0 + lj4);
        }
#pragma unroll
        for (int kk = 0; kk < 16; kk++) {
            float4 a = *(const float4*)&As[kk][ty * 4];
            float4 b = *(const float4*)&Bs[kk][tx * 4];
            ull aP0 = pack2(a.x, a.y);
            ull aP1 = pack2(a.z, a.w);
            ull bd;
            bd = pack2(b.x, b.x); ffma2(acc[0][0], aP0, bd); ffma2(acc[1][0], aP1, bd);
            bd = pack2(b.y, b.y); ffma2(acc[0][1], aP0, bd); ffma2(acc[1][1], aP1, bd);
            bd = pack2(b.z, b.z); ffma2(acc[0][2], aP0, bd); ffma2(acc[1][2], aP1, bd);
            bd = pack2(b.w, b.w); ffma2(acc[0][3], aP0, bd); ffma2(acc[1][3], aP1, bd);
        }
        __syncthreads();
    }
#pragma unroll
    for (int p = 0; p < 2; p++)
#pragma unroll
        for (int j = 0; j < 4; j++) {
            float2 v = unpack2(acc[p][j]);
            const int row = m0 + ty * 4 + 2 * p;
            const int col = n0 + tx * 4 + j;
            float t0 = v.x + bias_s[tx * 4 + j];
            float t1 = v.y + bias_s[tx * 4 + j];
            g_delta[row * Dsz + col]       = (t0 > 20.0f) ? t0 : log1pf(expf(t0));
            g_delta[(row + 1) * Dsz + col] = (t1 > 20.0f) ? t1 : log1pf(expf(t1));
        }
}

// ---------------- elem: streaming state update, h0 coalesced ----------------
// grid = (20, 32): d-chunk 256, b-chunk 8. Quad-of-lanes per d, 4 n per lane.
__global__ void __launch_bounds__(256) elem_kernel(const float* __restrict__ x,
                                                   const float* __restrict__ Ag,
                                                   const float* __restrict__ Dg,
                                                   const float* __restrict__ h0,
                                                   float* __restrict__ out)
{
    __shared__ float Cp_s[8][16];
    __shared__ float BC_s[8];

    const int d0 = blockIdx.x * 256;
    const int b0 = blockIdx.y * 8;
    const int tid = threadIdx.x;
    const int nq = tid & 3;       // n-quad (0..3)
    const int dq = tid >> 2;      // local d (0..63)

    if (tid < 128) {
        const int bb = tid >> 4, n = tid & 15;
        Cp_s[bb][n] = g_TBC[(b0 + bb) * NC + 176 + n];
    }
    __syncthreads();
    if (tid < 8) {
        float s = 0.0f;
#pragma unroll
        for (int n = 0; n < 16; n++)
            s += g_TBC[(b0 + tid) * NC + 160 + n] * Cp_s[tid][n];
        BC_s[tid] = s;
    }
    __syncthreads();

#pragma unroll
    for (int i = 0; i < 4; i++) {
        const int d = d0 + i * 64 + dq;
        const float4 Av = *(const float4*)(Ag + d * 16 + nq * 4);
        const float Dv = Dg[d];
#pragma unroll
        for (int b = 0; b < 8; b++) {
            const int gb = b0 + b;
            const size_t base = (size_t)gb * Dsz + d;
            const float4 h = *(const float4*)(h0 + base * 16 + nq * 4);
            const float delta = g_delta[base];
            const float* Cr = &Cp_s[b][nq * 4];
            float y = __expf(delta * Av.x) * (h.x * Cr[0])
                    + __expf(delta * Av.y) * (h.y * Cr[1])
                    + __expf(delta * Av.z) * (h.z * Cr[2])
                    + __expf(delta * Av.w) * (h.w * Cr[3]);
            y += __shfl_xor_sync(0xffffffffu, y, 1);
            y += __shfl_xor_sync(0xffffffffu, y, 2);
            if (nq == 0) {
                const float xv = x[base];
                out[base] = xv * (Dv + delta * BC_s[b]) + y;
            }
        }
    }
}

extern "C" void kernel_launch(void* const* d_in, const int* in_sizes, int n_in,
                              void* d_out, int out_size) {
    const float* x    = (const float*)d_in[0];
    const float* Wlow = (const float*)d_in[1];
    const float* Wdt  = (const float*)d_in[2];
    const float* bdt  = (const float*)d_in[3];
    const float* WB   = (const float*)d_in[4];
    const float* WC   = (const float*)d_in[5];
    const float* A    = (const float*)d_in[6];
    const float* D    = (const float*)d_in[7];
    const float* h0   = (const float*)d_in[8];
    float* out = (float*)d_out;

    prep_kernel<<<(Dsz * NC + Bsz * NC + 255) / 256, 256>>>(Wlow, WB, WC);
    gemm1_kernel<<<dim3(12, 40), 256>>>(x);
    gemm2_kernel<<<dim3(80, 4), 256>>>(Wdt, bdt);
    elem_kernel<<<dim3(20, 32), 256>>>(x, A, D, h0, out);
}

// round 5
// speedup vs baseline: 1.7930x; 1.2446x over previous
#include <cuda_runtime.h>
#include <math.h>

// TtMambaSSM (B=256, D=5120, R=160, N=16)
//   prep  : Wcat = [W_dt_low | W_B | W_C] (5120 x 192, float4), zero TBC
//   gemm1 : TBC = x @ Wcat                 (256 x 192, split-K=40 + atomics, dbl-buffered)
//   gemm2 : delta = softplus(T @ W_dt + b) (256 x 5120, dbl-buffered)
//   elem  : out = x*(D + delta*BC) + sum_n exp(delta*A)*h0*Cp  (h0 MLP=8, coalesced)

typedef unsigned long long ull;

#define Bsz 256
#define Dsz 5120
#define NC  192

__device__ float g_Wcat[Dsz * NC];
__device__ float g_TBC[Bsz * NC];
__device__ float g_delta[Bsz * Dsz];

__device__ __forceinline__ ull pack2(float lo, float hi) {
    ull r; asm("mov.b64 %0, {%1, %2};" : "=l"(r) : "f"(lo), "f"(hi)); return r;
}
__device__ __forceinline__ void ffma2(ull& d, ull a, ull b) {
    asm("fma.rn.f32x2 %0, %1, %2, %0;" : "+l"(d) : "l"(a), "l"(b));
}
__device__ __forceinline__ float2 unpack2(ull v) {
    float2 f; asm("mov.b64 {%0, %1}, %2;" : "=f"(f.x), "=f"(f.y) : "l"(v)); return f;
}

// ---------------- prep: concat weights (float4) + zero accumulator ----------------
__global__ void prep_kernel(const float* __restrict__ Wlow,
                            const float* __restrict__ WB,
                            const float* __restrict__ WC)
{
    int q = blockIdx.x * 256 + threadIdx.x;          // quad index
    const int NQ = Dsz * NC / 4;
    if (q < NQ) {
        int k = q / (NC / 4), jq = q - k * (NC / 4); // jq: 0..47
        float4 w;
        if (jq < 40)      w = *(const float4*)(Wlow + k * 160 + jq * 4);
        else if (jq < 44) w = *(const float4*)(WB + k * 16 + (jq - 40) * 4);
        else              w = *(const float4*)(WC + k * 16 + (jq - 44) * 4);
        *(float4*)(g_Wcat + q * 4) = w;
    } else {
        int t = q - NQ;
        if (t < Bsz * NC / 4) *(float4*)(g_TBC + t * 4) = make_float4(0.f, 0.f, 0.f, 0.f);
    }
}

// ---------------- GEMM1: 256 x 192 x 5120, split-K=40, double-buffered ----------------
__global__ void __launch_bounds__(256) gemm1_kernel(const float* __restrict__ x)
{
    __shared__ float As[2][16][68];
    __shared__ float Bs[2][16][64];

    const int m0 = (blockIdx.x & 3) * 64;
    const int n0 = (blockIdx.x >> 2) * 64;
    const int k0 = blockIdx.y * 128;
    const int tid = threadIdx.x;
    const int ty = tid >> 4, tx = tid & 15;
    const int lm  = tid >> 2, lkq = (tid & 3) * 4;
    const int lkk = tid >> 4, lj4 = (tid & 15) * 4;

    ull acc[2][4];
    const ull z0 = pack2(0.0f, 0.0f);
#pragma unroll
    for (int p = 0; p < 2; p++)
#pragma unroll
        for (int j = 0; j < 4; j++) acc[p][j] = z0;

    float4 av = *(const float4*)(x + (m0 + lm) * Dsz + k0 + lkq);
    float4 bv = *(const float4*)(g_Wcat + (k0 + lkk) * NC + n0 + lj4);
    As[0][lkq + 0][lm] = av.x; As[0][lkq + 1][lm] = av.y;
    As[0][lkq + 2][lm] = av.z; As[0][lkq + 3][lm] = av.w;
    *(float4*)&Bs[0][lkk][lj4] = bv;
    __syncthreads();

    for (int it = 0; it < 8; it++) {
        const int cur = it & 1;
        if (it < 7) {
            const int kb = k0 + (it + 1) * 16;
            av = *(const float4*)(x + (m0 + lm) * Dsz + kb + lkq);
            bv = *(const float4*)(g_Wcat + (kb + lkk) * NC + n0 + lj4);
        }
#pragma unroll
        for (int kk = 0; kk < 16; kk++) {
            float4 a = *(const float4*)&As[cur][kk][ty * 4];
            float4 b = *(const float4*)&Bs[cur][kk][tx * 4];
            ull aP0 = pack2(a.x, a.y);
            ull aP1 = pack2(a.z, a.w);
            ull bd;
            bd = pack2(b.x, b.x); ffma2(acc[0][0], aP0, bd); ffma2(acc[1][0], aP1, bd);
            bd = pack2(b.y, b.y); ffma2(acc[0][1], aP0, bd); ffma2(acc[1][1], aP1, bd);
            bd = pack2(b.z, b.z); ffma2(acc[0][2], aP0, bd); ffma2(acc[1][2], aP1, bd);
            bd = pack2(b.w, b.w); ffma2(acc[0][3], aP0, bd); ffma2(acc[1][3], aP1, bd);
        }
        if (it < 7) {
            const int nxt = cur ^ 1;
            As[nxt][lkq + 0][lm] = av.x; As[nxt][lkq + 1][lm] = av.y;
            As[nxt][lkq + 2][lm] = av.z; As[nxt][lkq + 3][lm] = av.w;
            *(float4*)&Bs[nxt][lkk][lj4] = bv;
        }
        __syncthreads();
    }
#pragma unroll
    for (int p = 0; p < 2; p++)
#pragma unroll
        for (int j = 0; j < 4; j++) {
            float2 v = unpack2(acc[p][j]);
            const int row = m0 + ty * 4 + 2 * p;
            const int col = n0 + tx * 4 + j;
            atomicAdd(&g_TBC[row * NC + col], v.x);
            atomicAdd(&g_TBC[(row + 1) * NC + col], v.y);
        }
}

// ---------------- GEMM2: delta = softplus(T @ W_dt + b), double-buffered ----------------
__global__ void __launch_bounds__(256) gemm2_kernel(const float* __restrict__ Wdt,
                                                    const float* __restrict__ bias)
{
    __shared__ float As[2][16][68];
    __shared__ float Bs[2][16][64];
    __shared__ float bias_s[64];

    const int n0 = blockIdx.x * 64;
    const int m0 = blockIdx.y * 64;
    const int tid = threadIdx.x;
    const int ty = tid >> 4, tx = tid & 15;
    const int lm  = tid >> 2, lkq = (tid & 3) * 4;
    const int lkk = tid >> 4, lj4 = (tid & 15) * 4;

    if (tid < 64) bias_s[tid] = bias[n0 + tid];

    ull acc[2][4];
    const ull z0 = pack2(0.0f, 0.0f);
#pragma unroll
    for (int p = 0; p < 2; p++)
#pragma unroll
        for (int j = 0; j < 4; j++) acc[p][j] = z0;

    float4 av = *(const float4*)(g_TBC + (m0 + lm) * NC + lkq);
    float4 bv = *(const float4*)(Wdt + lkk * Dsz + n0 + lj4);
    As[0][lkq + 0][lm] = av.x; As[0][lkq + 1][lm] = av.y;
    As[0][lkq + 2][lm] = av.z; As[0][lkq + 3][lm] = av.w;
    *(float4*)&Bs[0][lkk][lj4] = bv;
    __syncthreads();

    for (int it = 0; it < 10; it++) {
        const int cur = it & 1;
        if (it < 9) {
            const int kb = (it + 1) * 16;
            av = *(const float4*)(g_TBC + (m0 + lm) * NC + kb + lkq);
            bv = *(const float4*)(Wdt + (kb + lkk) * Dsz + n0 + lj4);
        }
#pragma unroll
        for (int kk = 0; kk < 16; kk++) {
            float4 a = *(const float4*)&As[cur][kk][ty * 4];
            float4 b = *(const float4*)&Bs[cur][kk][tx * 4];
            ull aP0 = pack2(a.x, a.y);
            ull aP1 = pack2(a.z, a.w);
            ull bd;
            bd = pack2(b.x, b.x); ffma2(acc[0][0], aP0, bd); ffma2(acc[1][0], aP1, bd);
            bd = pack2(b.y, b.y); ffma2(acc[0][1], aP0, bd); ffma2(acc[1][1], aP1, bd);
            bd = pack2(b.z, b.z); ffma2(acc[0][2], aP0, bd); ffma2(acc[1][2], aP1, bd);
            bd = pack2(b.w, b.w); ffma2(acc[0][3], aP0, bd); ffma2(acc[1][3], aP1, bd);
        }
        if (it < 9) {
            const int nxt = cur ^ 1;
            As[nxt][lkq + 0][lm] = av.x; As[nxt][lkq + 1][lm] = av.y;
            As[nxt][lkq + 2][lm] = av.z; As[nxt][lkq + 3][lm] = av.w;
            *(float4*)&Bs[nxt][lkk][lj4] = bv;
        }
        __syncthreads();
    }
#pragma unroll
    for (int p = 0; p < 2; p++)
#pragma unroll
        for (int j = 0; j < 4; j++) {
            float2 v = unpack2(acc[p][j]);
            const int row = m0 + ty * 4 + 2 * p;
            const int col = n0 + tx * 4 + j;
            float t0 = v.x + bias_s[tx * 4 + j];
            float t1 = v.y + bias_s[tx * 4 + j];
            g_delta[row * Dsz + col]       = (t0 > 20.0f) ? t0 : log1pf(expf(t0));
            g_delta[(row + 1) * Dsz + col] = (t1 > 20.0f) ? t1 : log1pf(expf(t1));
        }
}

// ---------------- elem: h0 streamed with MLP=8, smem-staged delta/y ----------------
// grid = (20, 32): d-chunk 256, b-chunk 8. Lane quad per d, 4 states per lane.
__global__ void __launch_bounds__(256) elem_kernel(const float* __restrict__ x,
                                                   const float* __restrict__ Ag,
                                                   const float* __restrict__ Dg,
                                                   const float* __restrict__ h0,
                                                   float* __restrict__ out)
{
    __shared__ float delta_s[8 * 256];
    __shared__ float y_s[8 * 256];
    __shared__ float D_s[256];
    __shared__ float Cp_s[8][16];
    __shared__ float BC_s[8];

    const int d0 = blockIdx.x * 256;
    const int b0 = blockIdx.y * 8;
    const int tid = threadIdx.x;

    // stage delta (coalesced: b=r, d=tid since blockDim=256), D, Cp
#pragma unroll
    for (int r = 0; r < 8; r++)
        delta_s[r * 256 + tid] = g_delta[(size_t)(b0 + r) * Dsz + d0 + tid];
    D_s[tid] = Dg[d0 + tid];
    if (tid < 128) {
        const int bb = tid >> 4, n = tid & 15;
        Cp_s[bb][n] = g_TBC[(b0 + bb) * NC + 176 + n];
    }
    __syncthreads();
    if (tid < 8) {
        float s = 0.0f;
#pragma unroll
        for (int n = 0; n < 16; n++)
            s += g_TBC[(b0 + tid) * NC + 160 + n] * Cp_s[tid][n];
        BC_s[tid] = s;
    }
    __syncthreads();

    const int nq = tid & 3;       // state quad 0..3
    const int dq = tid >> 2;      // local d 0..63

#pragma unroll
    for (int i = 0; i < 4; i++) {
        const int dloc = i * 64 + dq;
        const int d = d0 + dloc;
        const float4 Av = *(const float4*)(Ag + d * 16 + nq * 4);
        // batch all 8 h0 loads -> MLP=8 per warp
        float4 hv[8];
#pragma unroll
        for (int b = 0; b < 8; b++)
            hv[b] = *(const float4*)(h0 + ((size_t)(b0 + b) * Dsz + d) * 16 + nq * 4);
#pragma unroll
        for (int b = 0; b < 8; b++) {
            const float delta = delta_s[b * 256 + dloc];
            const float* Cr = &Cp_s[b][nq * 4];
            float y = __expf(delta * Av.x) * (hv[b].x * Cr[0])
                    + __expf(delta * Av.y) * (hv[b].y * Cr[1])
                    + __expf(delta * Av.z) * (hv[b].z * Cr[2])
                    + __expf(delta * Av.w) * (hv[b].w * Cr[3]);
            y += __shfl_xor_sync(0xffffffffu, y, 1);
            y += __shfl_xor_sync(0xffffffffu, y, 2);
            if (nq == 0) y_s[b * 256 + dloc] = y;
        }
    }
    __syncthreads();

    // coalesced writeback with fused skip term (b=r, d=tid)
#pragma unroll
    for (int r = 0; r < 8; r++) {
        const int idx = r * 256 + tid;
        const size_t g = (size_t)(b0 + r) * Dsz + d0 + tid;
        out[g] = x[g] * (D_s[tid] + delta_s[idx] * BC_s[r]) + y_s[idx];
    }
}

extern "C" void kernel_launch(void* const* d_in, const int* in_sizes, int n_in,
                              void* d_out, int out_size) {
    const float* x    = (const float*)d_in[0];
    const float* Wlow = (const float*)d_in[1];
    const float* Wdt  = (const float*)d_in[2];
    const float* bdt  = (const float*)d_in[3];
    const float* WB   = (const float*)d_in[4];
    const float* WC   = (const float*)d_in[5];
    const float* A    = (const float*)d_in[6];
    const float* D    = (const float*)d_in[7];
    const float* h0   = (const float*)d_in[8];
    float* out = (float*)d_out;

    prep_kernel<<<((Dsz * NC + Bsz * NC) / 4 + 255) / 256, 256>>>(Wlow, WB, WC);
    gemm1_kernel<<<dim3(12, 40), 256>>>(x);
    gemm2_kernel<<<dim3(80, 4), 256>>>(Wdt, bdt);
    elem_kernel<<<dim3(20, 32), 256>>>(x, A, D, h0, out);
}